// round 13
// baseline (speedup 1.0000x reference)
#include <cuda_runtime.h>
#include <cuda_fp16.h>
#include <math.h>
#include <stdint.h>

#define PIX 4096
#define NV 9

// ---------------- scratch (device globals; half2 feature buffers) ------------
__device__ unsigned g_e1[32ull*16*PIX];     // encoder stage1, 32ch = 16 kpairs
__device__ unsigned g_e2[32ull*32*PIX];     // encoder stage2, 64ch = 32 kpairs
__device__ unsigned g_h0[2ull*36*32*PIX];   // ping-pong h0 (half2)
__device__ unsigned g_h1[2ull*36*32*PIX];   // ping-pong h1 (half2)
__device__ float    g_x [32ull*32*PIX*2];   // fp32 addend x, float2-interleaved
__device__ float    g_up[36ull*32*PIX*2];   // fp32 addend up (t=0 path only)
// pre-permuted half2 weights, kt-major conflict-free image (row stride 100 u32)
__device__ unsigned g_wp2 [144*100];
__device__ unsigned g_wp3 [288*100];
__device__ unsigned g_wpul[288*100];
__device__ unsigned g_wph0[288*100];
__device__ unsigned g_wph1[288*100];

// ---------------- helpers -----------------------------------------------------
__device__ __forceinline__ void cp16(uint32_t s, const void* g, int srcsz) {
    asm volatile("cp.async.ca.shared.global [%0], [%1], 16, %2;"
                 :: "r"(s), "l"(g), "r"(srcsz));
}
__device__ __forceinline__ void cp8(uint32_t s, const void* g, int srcsz) {
    asm volatile("cp.async.ca.shared.global [%0], [%1], 8, %2;"
                 :: "r"(s), "l"(g), "r"(srcsz));
}
#define CP_COMMIT() asm volatile("cp.async.commit_group;")
#define CP_WAIT0()  asm volatile("cp.async.wait_group 0;" ::: "memory")

__device__ __forceinline__ void mma16(float* d, unsigned a0, unsigned a1,
                                      unsigned a2, unsigned a3,
                                      unsigned b0, unsigned b1) {
    asm("mma.sync.aligned.m16n8k16.row.col.f32.f16.f16.f32 "
        "{%0,%1,%2,%3},{%4,%5,%6,%7},{%8,%9},{%0,%1,%2,%3};"
        : "+f"(d[0]), "+f"(d[1]), "+f"(d[2]), "+f"(d[3])
        : "r"(a0), "r"(a1), "r"(a2), "r"(a3), "r"(b0), "r"(b1));
}
__device__ __forceinline__ unsigned packh(float a, float b) {
    __half2 h = __halves2half2(__float2half_rn(a), __float2half_rn(b));
    return *(unsigned*)&h;
}
__device__ __forceinline__ unsigned long long ffma2(unsigned long long a,
                                                    unsigned long long b,
                                                    unsigned long long c) {
    unsigned long long d;
    asm("fma.rn.f32x2 %0, %1, %2, %3;" : "=l"(d) : "l"(a), "l"(b), "l"(c));
    return d;
}
__device__ __forceinline__ unsigned long long pack_dup(float v) {
    unsigned long long d; unsigned r = __float_as_uint(v);
    asm("mov.b64 %0, {%1, %1};" : "=l"(d) : "r"(r));
    return d;
}
__device__ __forceinline__ void unpack2(unsigned long long v, float& lo, float& hi) {
    unsigned a, b;
    asm("mov.b64 {%0, %1}, %2;" : "=r"(a), "=r"(b) : "l"(v));
    lo = __uint_as_float(a); hi = __uint_as_float(b);
}
__constant__ float BNS_C = 0.9999950000374996f;   // 1/sqrt(1+1e-5)

// weights -> half2, kt-major: row = (kt*9+tap)*8+kp8 (stride 100), col gid*12+g
__global__ void prep_w_k(const float* __restrict__ w2, const float* __restrict__ w3,
                         const float* __restrict__ wul, const float* __restrict__ wh0,
                         const float* __restrict__ wh1) {
    int idx = blockIdx.x * 256 + threadIdx.x, conv = blockIdx.y;
    const float* src; unsigned* dst; int CIN;
    if      (conv == 0) { src = w2;  dst = g_wp2;  CIN = 32; }
    else if (conv == 1) { src = w3;  dst = g_wp3;  CIN = 64; }
    else if (conv == 2) { src = wul; dst = g_wpul; CIN = 64; }
    else if (conv == 3) { src = wh0; dst = g_wph0; CIN = 64; }
    else                { src = wh1; dst = g_wph1; CIN = 64; }
    int KP = CIN >> 1;
    if (idx >= 9 * KP * 64) return;
    int tap = idx / (KP * 64), rem = idx - tap * (KP * 64);
    int kp = rem >> 6, n = rem & 63;
    int kt = kp >> 3, kp8 = kp & 7, gid = n & 7, g = n >> 3;
    float lo = src[((size_t)n * CIN + 2 * kp) * 9 + tap];
    float hi = src[((size_t)n * CIN + 2 * kp + 1) * 9 + tap];
    dst[((kt * 9 + tap) * 8 + kp8) * 100 + gid * 12 + g] = packh(lo, hi);
}

// ---------------- encoder conv1: 3->32, 5x5, quad-tiled f32x2 ----------------
__global__ void __launch_bounds__(256, 1)
conv1q_k(const float* __restrict__ u, const float* __restrict__ wt,
         const float* __restrict__ gm, const float* __restrict__ bt,
         unsigned* __restrict__ out) {
    __shared__ float sIn[3][1296];    // 3 x 36x36 (halo 2)
    __shared__ float sW[2400];        // [cin][tap25][cout32]
    int tile = blockIdx.x, e = blockIdx.y;      // e = t*4+b
    int tstep = e >> 2, bb = e & 3;
    int ty0 = (tile >> 1) << 5, tx0 = (tile & 1) << 5;
    int tid = threadIdx.x, lx = tid & 15, ly = tid >> 4;
    int qy = ly << 1, qx = lx << 1;
    const float* inI = u + (size_t)(bb * 8 + tstep) * 3 * PIX;
    for (int i = tid; i < 2400; i += 256) {
        int k = i / 800, r = i - k * 800, t5 = r >> 5, c = r & 31;
        sW[i] = wt[(c * 3 + k) * 25 + t5];
    }
    for (int i = tid; i < 3 * 1296; i += 256) {
        int k = i / 1296, rem = i - k * 1296, ry = rem / 36, rx = rem - ry * 36;
        int gy = ty0 + ry - 2, gx = tx0 + rx - 2;
        sIn[k][rem] = (gy >= 0 && gy < 64 && gx >= 0 && gx < 64)
                      ? inI[(size_t)k * PIX + gy * 64 + gx] : 0.f;
    }
    __syncthreads();

    unsigned long long acc[16][4];
#pragma unroll
    for (int p = 0; p < 16; p++)
#pragma unroll
        for (int j = 0; j < 4; j++) acc[p][j] = 0ull;

    for (int k = 0; k < 3; k++) {
        unsigned long long n2[36];
#pragma unroll
        for (int dy = 0; dy < 6; dy++)
#pragma unroll
            for (int dx = 0; dx < 6; dx++)
                n2[dy * 6 + dx] = pack_dup(sIn[k][(qy + dy) * 36 + qx + dx]);
#pragma unroll
        for (int t5 = 0; t5 < 25; t5++) {
            int dy = t5 / 5, dx = t5 - dy * 5;
            const unsigned long long* w2p =
                (const unsigned long long*)(sW + k * 800 + t5 * 32);
#pragma unroll
            for (int p = 0; p < 16; p++) {
                unsigned long long w = w2p[p];
#pragma unroll
                for (int py = 0; py < 2; py++)
#pragma unroll
                    for (int pxx = 0; pxx < 2; pxx++)
                        acc[p][py * 2 + pxx] =
                            ffma2(w, n2[(py + dy) * 6 + (pxx + dx)], acc[p][py * 2 + pxx]);
            }
        }
    }
    unsigned* o = out + (size_t)e * 16 * PIX;
#pragma unroll
    for (int p = 0; p < 16; p++) {
        int c = 2 * p;
        float s0 = gm[c] * BNS_C, o0 = bt[c];
        float s1 = gm[c + 1] * BNS_C, o1 = bt[c + 1];
#pragma unroll
        for (int py = 0; py < 2; py++)
#pragma unroll
            for (int pxx = 0; pxx < 2; pxx++) {
                float lo, hi;
                unpack2(acc[p][py * 2 + pxx], lo, hi);
                float r0 = fmaxf(lo * s0 + o0, 0.f), r1 = fmaxf(hi * s1 + o1, 0.f);
                o[(size_t)p * PIX + (ty0 + qy + py) * 64 + tx0 + qx + pxx] = packh(r0, r1);
            }
    }
}

// ---------------- t=0 shortcuts ----------------------------------------------
__global__ void h0t0_k(const float* __restrict__ x, unsigned* __restrict__ h0) {
    int b = blockIdx.y;
    int i = blockIdx.x * 256 + threadIdx.x;          // < 32*PIX
    float2 xv = ((const float2*)x)[(size_t)b * 32 * PIX + i];
    unsigned hv = packh(tanhf(xv.x), tanhf(xv.y));
#pragma unroll
    for (int v = 0; v < 9; v++)
        h0[((size_t)(b * 9 + v) * 32) * PIX + i] = hv;
}
__global__ void h1t0_k(const float* __restrict__ up, unsigned* __restrict__ h1,
                       float* __restrict__ dout) {
    int b = blockIdx.y;
    int i = blockIdx.x * 256 + threadIdx.x;          // kp*PIX + pix
    int kp = i >> 12, pix = i & 4095, c = kp * 2;
    float2 uv = ((const float2*)up)[((size_t)(b * 9) * 32 + kp) * PIX + pix];
    float t0 = tanhf(uv.x), t1 = tanhf(uv.y);
    unsigned hv = packh(t0, t1);
#pragma unroll
    for (int v = 0; v < 9; v++) {
        h1[((size_t)(b * 9 + v) * 32 + kp) * PIX + pix] = hv;
        float* q = dout + (((size_t)(v * 4 + b) * 64 + c) * 8) * PIX;
        q[pix] = t0; q[8 * PIX + pix] = t1;
    }
}

// ---------------- shared staging: 8 rows (4-row tile + halo 2) ---------------
// A layout: [kp][584] (8 rows x 72 cols + 8 pad; 584 % 32 == 8, conflict-free)
template <int KP>
__device__ __forceinline__ void stage_a(uint32_t smA, const unsigned* inI,
                                        int ry0, bool circ, int tid) {
    for (int i = tid; i < KP * 144; i += 256) {
        int k = i / 144, rem = i - k * 144, r = rem / 18, s = rem - r * 18;
        int gy = ry0 + r - 2;
        bool rowok = true;
        if (circ) gy &= 63; else rowok = (gy >= 0 && gy < 64);
        const unsigned* srow = inI + (size_t)k * PIX + gy * 64;
        uint32_t dst = smA + (uint32_t)(k * 584 + r * 72) * 4u;
        if (s < 16)       cp16(dst + (4 + s * 4) * 4, srow + s * 4, rowok ? 16 : 0);
        else if (s == 16) cp8(dst + 2 * 4, srow + 62, (circ && rowok) ? 8 : 0);
        else              cp8(dst + 68 * 4, srow,     (circ && rowok) ? 8 : 0);
    }
}

// mainloop over KT kt-chunks with W streamed per-kt through one 28.8KB buffer
template <int KT>
__device__ __forceinline__ void mainloop_ws(const unsigned* As, const unsigned* Ws,
                                            uint32_t smW, const unsigned* wp,
                                            int mbase, int vy, int vx,
                                            int qt, int qp, int tid,
                                            float acc[2][8][4]) {
    for (int kt = 0; kt < KT; kt++) {
        if (kt) __syncthreads();                       // done reading prev W
        for (int i = tid; i < 1800; i += 256)          // 72 rows x 25 uint4
            cp16(smW + i * 16, wp + ((size_t)kt * 1800 + i) * 4, 16);
        CP_COMMIT(); CP_WAIT0(); __syncthreads();
#pragma unroll
        for (int tap = 0; tap < 9; tap++) {
            int dy = tap / 3, dx = tap - dy * 3;
            int apos = mbase + (dy - 1 + vy) * 72 + (dx - 1 + vx);
            int wr = (tap * 8 + qt) * 100 + qp * 12;
            uint4 L0 = *(const uint4*)(Ws + wr);
            uint4 L1 = *(const uint4*)(Ws + wr + 4);
            uint4 L2 = *(const uint4*)(Ws + wr + 4 * 100);
            uint4 L3 = *(const uint4*)(Ws + wr + 4 * 100 + 4);
            unsigned b0[8] = {L0.x, L0.y, L0.z, L0.w, L1.x, L1.y, L1.z, L1.w};
            unsigned b1[8] = {L2.x, L2.y, L2.z, L2.w, L3.x, L3.y, L3.z, L3.w};
            int ar0 = (kt * 8 + qt) * 584, ar2 = ar0 + 4 * 584;
#pragma unroll
            for (int mt = 0; mt < 2; mt++) {
                int base = apos + mt * 16;
                unsigned a0 = As[ar0 + base], a1 = As[ar0 + base + 8];
                unsigned a2 = As[ar2 + base], a3 = As[ar2 + base + 8];
#pragma unroll
                for (int g = 0; g < 8; g++)
                    mma16(acc[mt][g], a0, a1, a2, a3, b0[g], b1[g]);
            }
        }
    }
}

// ---------------- fp16 tensor-core 3x3 conv, CIN->64, 2 CTAs/SM --------------
// Block 256 thr = 8 warps; 4 output rows x 64 px; warp = (row 0..3, xhalf).
// EPI 0: BN+ReLU -> half2   EPI 1: BN+ReLU -> float2 addend
// EPI 2: tanh(acc + x) -> half2
template <int CIN, bool CIRC, int EPI>
__global__ void __launch_bounds__(256, 2)
convh_k(const unsigned* __restrict__ in, const unsigned* __restrict__ wp,
        const float* __restrict__ gm, const float* __restrict__ bt,
        const float* __restrict__ add, unsigned* __restrict__ outH,
        float* __restrict__ outF, int tstep, int imgstep) {
    constexpr int KP = CIN / 2, KT = CIN / 16;
    extern __shared__ unsigned smu[];
    unsigned* As = smu;                  // [KP][584]
    unsigned* Ws = smu + KP * 584;       // [72 rows][100] current kt chunk

    int img = blockIdx.y * imgstep, ry0 = blockIdx.x * 4;
    int tid = threadIdx.x;
    int w = tid >> 5, qp = (tid >> 2) & 7, qt = tid & 3;
    int row = w >> 1, xhalf = w & 1;
    int vy = 0, vx = 0;
    if (CIRC) { int v = img % NV; vy = v / 3 - 1; vx = v % 3 - 1; }
    const unsigned* inI = in + (size_t)img * KP * PIX;
    uint32_t smA = (uint32_t)__cvta_generic_to_shared(As);
    uint32_t smW = (uint32_t)__cvta_generic_to_shared(Ws);

    stage_a<KP>(smA, inI, ry0, CIRC, tid);
    CP_COMMIT();

    float acc[2][8][4];
#pragma unroll
    for (int mt = 0; mt < 2; mt++)
#pragma unroll
        for (int g = 0; g < 8; g++)
#pragma unroll
            for (int j = 0; j < 4; j++) acc[mt][g][j] = 0.f;

    int mbase = (2 + row) * 72 + 4 + 32 * xhalf + qp;
    mainloop_ws<KT>(As, Ws, smW, wp, mbase, vy, vx, qt, qp, tid, acc);

    // ---- epilogue ----
    int y = ry0 + row;
#pragma unroll
    for (int mt = 0; mt < 2; mt++) {
        int x0 = 32 * xhalf + qp + mt * 16;
        int pixA = y * 64 + x0, pixB = pixA + 8;
#pragma unroll
        for (int g = 0; g < 8; g++) {
            int kp = g * 4 + qt, c = kp * 2;
            float v0 = acc[mt][g][0], v1 = acc[mt][g][1];
            float v2 = acc[mt][g][2], v3 = acc[mt][g][3];
            if (EPI == 0 || EPI == 1) {
                float s0 = gm[c] * BNS_C, s1 = gm[c+1] * BNS_C;
                float o0 = bt[c], o1 = bt[c+1];
                v0 = fmaxf(v0 * s0 + o0, 0.f); v1 = fmaxf(v1 * s1 + o1, 0.f);
                v2 = fmaxf(v2 * s0 + o0, 0.f); v3 = fmaxf(v3 * s1 + o1, 0.f);
                if (EPI == 0) {
                    unsigned* o = outH + ((size_t)img * 32 + kp) * PIX;
                    o[pixA] = packh(v0, v1); o[pixB] = packh(v2, v3);
                } else {
                    float2* o = (float2*)outF + ((size_t)img * 32 + kp) * PIX;
                    o[pixA] = make_float2(v0, v1); o[pixB] = make_float2(v2, v3);
                }
            } else {
                const float2* a = (const float2*)add +
                    ((size_t)(tstep * 4 + img / NV) * 32 + kp) * PIX;
                float2 xa = a[pixA], xb = a[pixB];
                float t0 = tanhf(v0 + xa.x), t1 = tanhf(v1 + xa.y);
                float t2 = tanhf(v2 + xb.x), t3 = tanhf(v3 + xb.y);
                unsigned* o = outH + ((size_t)img * 32 + kp) * PIX;
                o[pixA] = packh(t0, t1); o[pixB] = packh(t2, t3);
            }
        }
    }
}

// ---------------- fused up+h1 kernel (same 4-row tile, W streamed) -----------
__global__ void __launch_bounds__(256, 2)
convfuse_k(const unsigned* __restrict__ h0new, const unsigned* __restrict__ h1old,
           const unsigned* __restrict__ wpul, const unsigned* __restrict__ wph1,
           const float* __restrict__ gul, const float* __restrict__ bul,
           unsigned* __restrict__ h1out, float* __restrict__ dout, int tstep) {
    extern __shared__ unsigned smu[];
    unsigned* As = smu;                  // [32][584]
    unsigned* Ws = smu + 32 * 584;       // [72 rows][100]

    int img = blockIdx.y, ry0 = blockIdx.x * 4;
    int tid = threadIdx.x;
    int w = tid >> 5, qp = (tid >> 2) & 7, qt = tid & 3;
    int row = w >> 1, xhalf = w & 1;
    int v = img % NV, vy = v / 3 - 1, vx = v % 3 - 1;
    uint32_t smA = (uint32_t)__cvta_generic_to_shared(As);
    uint32_t smW = (uint32_t)__cvta_generic_to_shared(Ws);
    int mbase = (2 + row) * 72 + 4 + 32 * xhalf + qp;

    // ---- phase 1: conv_ul on h0new (zero pad, no shift) ----
    stage_a<32>(smA, h0new + (size_t)img * 32 * PIX, ry0, false, tid);
    CP_COMMIT();
    float acc[2][8][4];
#pragma unroll
    for (int mt = 0; mt < 2; mt++)
#pragma unroll
        for (int g = 0; g < 8; g++)
#pragma unroll
            for (int j = 0; j < 4; j++) acc[mt][g][j] = 0.f;
    mainloop_ws<4>(As, Ws, smW, wpul, mbase, 0, 0, qt, qp, tid, acc);

    // bn/relu -> up local array (spills to L1-resident local; intended)
    float upl[64];
#pragma unroll
    for (int mt = 0; mt < 2; mt++)
#pragma unroll
        for (int g = 0; g < 8; g++) {
            int c = (g * 4 + qt) * 2;
            float s0 = gul[c] * BNS_C, s1 = gul[c + 1] * BNS_C;
            float o0 = bul[c], o1 = bul[c + 1];
            upl[mt * 32 + g * 4 + 0] = fmaxf(acc[mt][g][0] * s0 + o0, 0.f);
            upl[mt * 32 + g * 4 + 1] = fmaxf(acc[mt][g][1] * s1 + o1, 0.f);
            upl[mt * 32 + g * 4 + 2] = fmaxf(acc[mt][g][2] * s0 + o0, 0.f);
            upl[mt * 32 + g * 4 + 3] = fmaxf(acc[mt][g][3] * s1 + o1, 0.f);
        }
    __syncthreads();     // all warps done reading As

    // ---- phase 2: conv_h1 on h1old (circular + velocity shift) ----
    stage_a<32>(smA, h1old + (size_t)img * 32 * PIX, ry0, true, tid);
    CP_COMMIT();
#pragma unroll
    for (int mt = 0; mt < 2; mt++)
#pragma unroll
        for (int g = 0; g < 8; g++)
#pragma unroll
            for (int j = 0; j < 4; j++) acc[mt][g][j] = 0.f;
    mainloop_ws<4>(As, Ws, smW, wph1, mbase, vy, vx, qt, qp, tid, acc);

    // ---- epilogue: h1 = tanh(acc + up); write h1 half2 + d_out fp32 ----
    int y = ry0 + row;
    int v9 = img % NV, bb = img / NV;
#pragma unroll
    for (int mt = 0; mt < 2; mt++) {
        int x0 = 32 * xhalf + qp + mt * 16;
        int pixA = y * 64 + x0, pixB = pixA + 8;
#pragma unroll
        for (int g = 0; g < 8; g++) {
            int kp = g * 4 + qt, c = kp * 2;
            float t0 = tanhf(acc[mt][g][0] + upl[mt * 32 + g * 4 + 0]);
            float t1 = tanhf(acc[mt][g][1] + upl[mt * 32 + g * 4 + 1]);
            float t2 = tanhf(acc[mt][g][2] + upl[mt * 32 + g * 4 + 2]);
            float t3 = tanhf(acc[mt][g][3] + upl[mt * 32 + g * 4 + 3]);
            unsigned* o = h1out + ((size_t)img * 32 + kp) * PIX;
            o[pixA] = packh(t0, t1); o[pixB] = packh(t2, t3);
            float* q = dout + (((size_t)(v9 * 4 + bb) * 64 + c) * 8 + tstep) * PIX;
            q[pixA] = t0; q[pixB] = t2;
            q += 8 * PIX;
            q[pixA] = t1; q[pixB] = t3;
        }
    }
}

// ---------------- host driver -------------------------------------------------
extern "C" void kernel_launch(void* const* d_in, const int* in_sizes, int n_in,
                              void* d_out, int out_size) {
    (void)in_sizes; (void)n_in; (void)out_size;
    const float* u   = (const float*)d_in[0];
    const float* w1  = (const float*)d_in[1];
    const float* g1  = (const float*)d_in[2];
    const float* b1  = (const float*)d_in[3];
    const float* w2  = (const float*)d_in[4];
    const float* g2  = (const float*)d_in[5];
    const float* b2  = (const float*)d_in[6];
    const float* w3  = (const float*)d_in[7];
    const float* g3  = (const float*)d_in[8];
    const float* b3  = (const float*)d_in[9];
    const float* wul = (const float*)d_in[10];
    const float* gul = (const float*)d_in[11];
    const float* bul = (const float*)d_in[12];
    const float* wh0 = (const float*)d_in[13];
    const float* wh1 = (const float*)d_in[14];
    float* out = (float*)d_out;

    const int SM64B = (32 * 584 + 7200) * 4;   // 103552
    const int SM32B = (16 * 584 + 7200) * 4;   //  66176

    static unsigned *pe1 = nullptr, *pe2, *ph0, *ph1,
                    *pw2, *pw3, *pwul, *pwh0, *pwh1;
    static float *px, *pup;
    if (!pe1) {   // pointer caching + attrs; runs on the pre-capture call
        cudaGetSymbolAddress((void**)&pe1,  g_e1);
        cudaGetSymbolAddress((void**)&pe2,  g_e2);
        cudaGetSymbolAddress((void**)&ph0,  g_h0);
        cudaGetSymbolAddress((void**)&ph1,  g_h1);
        cudaGetSymbolAddress((void**)&px,   g_x);
        cudaGetSymbolAddress((void**)&pup,  g_up);
        cudaGetSymbolAddress((void**)&pw2,  g_wp2);
        cudaGetSymbolAddress((void**)&pw3,  g_wp3);
        cudaGetSymbolAddress((void**)&pwul, g_wpul);
        cudaGetSymbolAddress((void**)&pwh0, g_wph0);
        cudaGetSymbolAddress((void**)&pwh1, g_wph1);
        cudaFuncSetAttribute(convh_k<32, false, 0>,
                             cudaFuncAttributeMaxDynamicSharedMemorySize, SM32B);
        cudaFuncSetAttribute(convh_k<64, false, 1>,
                             cudaFuncAttributeMaxDynamicSharedMemorySize, SM64B);
        cudaFuncSetAttribute(convh_k<64, true, 2>,
                             cudaFuncAttributeMaxDynamicSharedMemorySize, SM64B);
        cudaFuncSetAttribute(convfuse_k,
                             cudaFuncAttributeMaxDynamicSharedMemorySize, SM64B);
    }
    const size_t HSZ = 36ull * 32 * PIX;   // h buffer parity size (u32 units)

    prep_w_k<<<dim3(72, 5), 256>>>(w2, w3, wul, wh0, wh1);

    // encoder
    conv1q_k<<<dim3(4, 32), 256>>>(u, w1, g1, b1, pe1);
    convh_k<32, false, 0><<<dim3(16, 32), 256, SM32B>>>(
        pe1, pw2, g2, b2, nullptr, pe2, nullptr, 0, 1);
    convh_k<64, false, 1><<<dim3(16, 32), 256, SM64B>>>(
        pe2, pw3, g3, b3, nullptr, nullptr, px, 0, 1);

    // ---- t = 0 (hidden states zero): algebraic shortcut ----
    h0t0_k<<<dim3(512, 4), 256>>>(px, ph0 + HSZ);                 // parity 1
    convh_k<64, false, 1><<<dim3(16, 4), 256, SM64B>>>(           // up_0, 4 imgs
        ph0 + HSZ, pwul, gul, bul, nullptr, nullptr, pup, 0, 9);
    h1t0_k<<<dim3(512, 4), 256>>>(pup, ph1 + HSZ, out);           // parity 1

    // ---- recurrent steps t = 1..7 ----
    for (int t = 1; t < 8; t++) {
        int rp = t & 1, wpp = 1 - rp;
        // h0 = tanh(x_t + circ-shift conv(h0_old, w_h0))
        convh_k<64, true, 2><<<dim3(16, 36), 256, SM64B>>>(
            ph0 + rp * HSZ, pwh0, nullptr, nullptr, px,
            ph0 + wpp * HSZ, nullptr, t, 1);
        // fused: up = relu(bn(conv_ul(h0_new))); h1 = tanh(up + conv_h1(h1_old))
        convfuse_k<<<dim3(16, 36), 256, SM64B>>>(
            ph0 + wpp * HSZ, ph1 + rp * HSZ, pwul, pwh1,
            gul, bul, ph1 + wpp * HSZ, out, t);
    }
}

// round 14
// speedup vs baseline: 1.1252x; 1.1252x over previous
#include <cuda_runtime.h>
#include <cuda_fp16.h>
#include <math.h>
#include <stdint.h>

#define PIX 4096
#define NV 9

// ---------------- scratch (device globals; half2 feature buffers) ------------
__device__ unsigned g_e1[32ull*16*PIX];     // encoder stage1, 32ch = 16 kpairs
__device__ unsigned g_e2[32ull*32*PIX];     // encoder stage2, 64ch = 32 kpairs
__device__ unsigned g_h0[2ull*36*32*PIX];   // ping-pong h0 (half2)
__device__ unsigned g_h1[2ull*36*32*PIX];   // ping-pong h1 (half2)
__device__ float    g_x [32ull*32*PIX*2];   // fp32 addend x, float2-interleaved
__device__ float    g_up[36ull*32*PIX*2];   // fp32 addend up (t=0 path only)
// pre-permuted half2 weights, kt-major conflict-free image (row stride 100 u32)
__device__ unsigned g_wp2 [144*100];
__device__ unsigned g_wp3 [288*100];
__device__ unsigned g_wpul[288*100];
__device__ unsigned g_wph0[288*100];
__device__ unsigned g_wph1[288*100];

// ---------------- helpers -----------------------------------------------------
__device__ __forceinline__ void cp16(uint32_t s, const void* g, int srcsz) {
    asm volatile("cp.async.cg.shared.global [%0], [%1], 16, %2;"
                 :: "r"(s), "l"(g), "r"(srcsz));
}
__device__ __forceinline__ void cp8(uint32_t s, const void* g, int srcsz) {
    asm volatile("cp.async.ca.shared.global [%0], [%1], 8, %2;"
                 :: "r"(s), "l"(g), "r"(srcsz));
}
#define CP_COMMIT() asm volatile("cp.async.commit_group;")
#define CP_WAIT1()  asm volatile("cp.async.wait_group 1;" ::: "memory")
#define CP_WAIT0()  asm volatile("cp.async.wait_group 0;" ::: "memory")

__device__ __forceinline__ void mma16(float* d, unsigned a0, unsigned a1,
                                      unsigned a2, unsigned a3,
                                      unsigned b0, unsigned b1) {
    asm("mma.sync.aligned.m16n8k16.row.col.f32.f16.f16.f32 "
        "{%0,%1,%2,%3},{%4,%5,%6,%7},{%8,%9},{%0,%1,%2,%3};"
        : "+f"(d[0]), "+f"(d[1]), "+f"(d[2]), "+f"(d[3])
        : "r"(a0), "r"(a1), "r"(a2), "r"(a3), "r"(b0), "r"(b1));
}
__device__ __forceinline__ unsigned packh(float a, float b) {
    __half2 h = __halves2half2(__float2half_rn(a), __float2half_rn(b));
    return *(unsigned*)&h;
}
__device__ __forceinline__ float tanh_ap(float x) {
    float r;
    asm("tanh.approx.f32 %0, %1;" : "=f"(r) : "f"(x));
    return r;
}
__device__ __forceinline__ unsigned long long ffma2(unsigned long long a,
                                                    unsigned long long b,
                                                    unsigned long long c) {
    unsigned long long d;
    asm("fma.rn.f32x2 %0, %1, %2, %3;" : "=l"(d) : "l"(a), "l"(b), "l"(c));
    return d;
}
__device__ __forceinline__ unsigned long long pack_dup(float v) {
    unsigned long long d; unsigned r = __float_as_uint(v);
    asm("mov.b64 %0, {%1, %1};" : "=l"(d) : "r"(r));
    return d;
}
__device__ __forceinline__ void unpack2(unsigned long long v, float& lo, float& hi) {
    unsigned a, b;
    asm("mov.b64 {%0, %1}, %2;" : "=r"(a), "=r"(b) : "l"(v));
    lo = __uint_as_float(a); hi = __uint_as_float(b);
}
__constant__ float BNS_C = 0.9999950000374996f;   // 1/sqrt(1+1e-5)

// weights -> half2, kt-major: row = (kt*9+tap)*8+kp8 (stride 100), col gid*12+g
__global__ void prep_w_k(const float* __restrict__ w2, const float* __restrict__ w3,
                         const float* __restrict__ wul, const float* __restrict__ wh0,
                         const float* __restrict__ wh1) {
    int idx = blockIdx.x * 256 + threadIdx.x, conv = blockIdx.y;
    const float* src; unsigned* dst; int CIN;
    if      (conv == 0) { src = w2;  dst = g_wp2;  CIN = 32; }
    else if (conv == 1) { src = w3;  dst = g_wp3;  CIN = 64; }
    else if (conv == 2) { src = wul; dst = g_wpul; CIN = 64; }
    else if (conv == 3) { src = wh0; dst = g_wph0; CIN = 64; }
    else                { src = wh1; dst = g_wph1; CIN = 64; }
    int KP = CIN >> 1;
    if (idx >= 9 * KP * 64) return;
    int tap = idx / (KP * 64), rem = idx - tap * (KP * 64);
    int kp = rem >> 6, n = rem & 63;
    int kt = kp >> 3, kp8 = kp & 7, gid = n & 7, g = n >> 3;
    float lo = src[((size_t)n * CIN + 2 * kp) * 9 + tap];
    float hi = src[((size_t)n * CIN + 2 * kp + 1) * 9 + tap];
    dst[((kt * 9 + tap) * 8 + kp8) * 100 + gid * 12 + g] = packh(lo, hi);
}

// ---------------- encoder conv1: 3->32, 5x5, quad-tiled f32x2 ----------------
__global__ void __launch_bounds__(256, 1)
conv1q_k(const float* __restrict__ u, const float* __restrict__ wt,
         const float* __restrict__ gm, const float* __restrict__ bt,
         unsigned* __restrict__ out) {
    __shared__ float sIn[3][1296];    // 3 x 36x36 (halo 2)
    __shared__ float sW[2400];        // [cin][tap25][cout32]
    int tile = blockIdx.x, e = blockIdx.y;      // e = t*4+b
    int tstep = e >> 2, bb = e & 3;
    int ty0 = (tile >> 1) << 5, tx0 = (tile & 1) << 5;
    int tid = threadIdx.x, lx = tid & 15, ly = tid >> 4;
    int qy = ly << 1, qx = lx << 1;
    const float* inI = u + (size_t)(bb * 8 + tstep) * 3 * PIX;
    for (int i = tid; i < 2400; i += 256) {
        int k = i / 800, r = i - k * 800, t5 = r >> 5, c = r & 31;
        sW[i] = wt[(c * 3 + k) * 25 + t5];
    }
    for (int i = tid; i < 3 * 1296; i += 256) {
        int k = i / 1296, rem = i - k * 1296, ry = rem / 36, rx = rem - ry * 36;
        int gy = ty0 + ry - 2, gx = tx0 + rx - 2;
        sIn[k][rem] = (gy >= 0 && gy < 64 && gx >= 0 && gx < 64)
                      ? inI[(size_t)k * PIX + gy * 64 + gx] : 0.f;
    }
    __syncthreads();

    unsigned long long acc[16][4];
#pragma unroll
    for (int p = 0; p < 16; p++)
#pragma unroll
        for (int j = 0; j < 4; j++) acc[p][j] = 0ull;

    for (int k = 0; k < 3; k++) {
        unsigned long long n2[36];
#pragma unroll
        for (int dy = 0; dy < 6; dy++)
#pragma unroll
            for (int dx = 0; dx < 6; dx++)
                n2[dy * 6 + dx] = pack_dup(sIn[k][(qy + dy) * 36 + qx + dx]);
#pragma unroll
        for (int t5 = 0; t5 < 25; t5++) {
            int dy = t5 / 5, dx = t5 - dy * 5;
            const unsigned long long* w2p =
                (const unsigned long long*)(sW + k * 800 + t5 * 32);
#pragma unroll
            for (int p = 0; p < 16; p++) {
                unsigned long long w = w2p[p];
#pragma unroll
                for (int py = 0; py < 2; py++)
#pragma unroll
                    for (int pxx = 0; pxx < 2; pxx++)
                        acc[p][py * 2 + pxx] =
                            ffma2(w, n2[(py + dy) * 6 + (pxx + dx)], acc[p][py * 2 + pxx]);
            }
        }
    }
    unsigned* o = out + (size_t)e * 16 * PIX;
#pragma unroll
    for (int p = 0; p < 16; p++) {
        int c = 2 * p;
        float s0 = gm[c] * BNS_C, o0 = bt[c];
        float s1 = gm[c + 1] * BNS_C, o1 = bt[c + 1];
#pragma unroll
        for (int py = 0; py < 2; py++)
#pragma unroll
            for (int pxx = 0; pxx < 2; pxx++) {
                float lo, hi;
                unpack2(acc[p][py * 2 + pxx], lo, hi);
                float r0 = fmaxf(lo * s0 + o0, 0.f), r1 = fmaxf(hi * s1 + o1, 0.f);
                o[(size_t)p * PIX + (ty0 + qy + py) * 64 + tx0 + qx + pxx] = packh(r0, r1);
            }
    }
}

// ---------------- t=0 shortcuts ----------------------------------------------
__global__ void h0t0_k(const float* __restrict__ x, unsigned* __restrict__ h0) {
    int b = blockIdx.y;
    int i = blockIdx.x * 256 + threadIdx.x;          // < 32*PIX
    float2 xv = ((const float2*)x)[(size_t)b * 32 * PIX + i];
    unsigned hv = packh(tanh_ap(xv.x), tanh_ap(xv.y));
#pragma unroll
    for (int v = 0; v < 9; v++)
        h0[((size_t)(b * 9 + v) * 32) * PIX + i] = hv;
}
__global__ void h1t0_k(const float* __restrict__ up, unsigned* __restrict__ h1,
                       float* __restrict__ dout) {
    int b = blockIdx.y;
    int i = blockIdx.x * 256 + threadIdx.x;          // kp*PIX + pix
    int kp = i >> 12, pix = i & 4095, c = kp * 2;
    float2 uv = ((const float2*)up)[((size_t)(b * 9) * 32 + kp) * PIX + pix];
    float t0 = tanh_ap(uv.x), t1 = tanh_ap(uv.y);
    unsigned hv = packh(t0, t1);
#pragma unroll
    for (int v = 0; v < 9; v++) {
        h1[((size_t)(b * 9 + v) * 32 + kp) * PIX + pix] = hv;
        float* q = dout + (((size_t)(v * 4 + b) * 64 + c) * 8) * PIX;
        q[pix] = t0; q[8 * PIX + pix] = t1;
    }
}

// ---------------- shared staging for 64-cin convs (KP=32) --------------------
__device__ __forceinline__ void stage_a64(uint32_t smA, const unsigned* inI,
                                          int ry0, bool circ, int k0, int k1,
                                          int tid, int nthr) {
    for (int i = k0 * 216 + tid; i < k1 * 216; i += nthr) {
        int k = i / 216, rem = i % 216, r = rem / 18, s = rem - r * 18;
        int gy = ry0 + r - 2;
        bool rowok = true;
        if (circ) gy &= 63; else rowok = (gy >= 0 && gy < 64);
        const unsigned* srow = inI + (size_t)k * PIX + gy * 64;
        uint32_t dst = smA + (uint32_t)(k * 872 + r * 72) * 4u;
        if (s < 16)       cp16(dst + (4 + s * 4) * 4, srow + s * 4, rowok ? 16 : 0);
        else if (s == 16) cp8(dst + 2 * 4, srow + 62, (circ && rowok) ? 8 : 0);
        else              cp8(dst + 68 * 4, srow,     (circ && rowok) ? 8 : 0);
    }
}

// mainloop for one 64-cin conv (KT=4); acc += conv
__device__ __forceinline__ void mainloop64(const unsigned* As, const unsigned* Ws,
                                           int mbase, int vy, int vx,
                                           int qt, int qp, float acc[2][8][4]) {
#pragma unroll
    for (int kt = 0; kt < 4; kt++) {
#pragma unroll
        for (int tap = 0; tap < 9; tap++) {
            int dy = tap / 3, dx = tap - dy * 3;
            int apos = mbase + (dy - 1 + vy) * 72 + (dx - 1 + vx);
            int wr = ((kt * 9 + tap) * 8 + qt) * 100 + qp * 12;
            uint4 L0 = *(const uint4*)(Ws + wr);
            uint4 L1 = *(const uint4*)(Ws + wr + 4);
            uint4 L2 = *(const uint4*)(Ws + wr + 4 * 100);
            uint4 L3 = *(const uint4*)(Ws + wr + 4 * 100 + 4);
            unsigned b0[8] = {L0.x, L0.y, L0.z, L0.w, L1.x, L1.y, L1.z, L1.w};
            unsigned b1[8] = {L2.x, L2.y, L2.z, L2.w, L3.x, L3.y, L3.z, L3.w};
            int ar0 = (kt * 8 + qt) * 872, ar2 = ar0 + 4 * 872;
#pragma unroll
            for (int mt = 0; mt < 2; mt++) {
                int base = apos + mt * 16;
                unsigned a0 = As[ar0 + base], a1 = As[ar0 + base + 8];
                unsigned a2 = As[ar2 + base], a3 = As[ar2 + base + 8];
#pragma unroll
                for (int g = 0; g < 8; g++)
                    mma16(acc[mt][g], a0, a1, a2, a3, b0[g], b1[g]);
            }
        }
    }
}

// ---------------- fp16 tensor-core 3x3 conv, CIN->64 (R9 config) -------------
// Block 512 thr = 16 warps; 8 output rows x 64 px; warp = (row 0..7, xhalf).
// EPI 0: BN+ReLU -> half2    EPI 1: BN+ReLU -> float2 addend
// EPI 2: tanh(acc + x) -> half2
template <int CIN, bool CIRC, int EPI>
__global__ void __launch_bounds__(512, 1)
convh_k(const unsigned* __restrict__ in, const unsigned* __restrict__ wp,
        const float* __restrict__ gm, const float* __restrict__ bt,
        const float* __restrict__ add, unsigned* __restrict__ outH,
        float* __restrict__ outF, int tstep, int imgstep) {
    constexpr int KP = CIN / 2, KT = CIN / 16, KPH = KP / 2;
    constexpr int WHALF = (KT / 2) * 9 * 8 * 25;     // uint4 per W half
    extern __shared__ unsigned smu[];
    unsigned* As = smu;                  // [KP][872]
    unsigned* Ws = smu + KP * 872;       // [KT*9*8 rows][100]

    int img = blockIdx.y * imgstep, ry0 = blockIdx.x * 8;
    int tid = threadIdx.x;
    int w = tid >> 5, qp = (tid >> 2) & 7, qt = tid & 3;
    int row = w >> 1, xhalf = w & 1;
    int vy = 0, vx = 0;
    if (CIRC) { int v = img % NV; vy = v / 3 - 1; vx = v % 3 - 1; }
    const unsigned* inI = in + (size_t)img * KP * PIX;
    uint32_t smA = (uint32_t)__cvta_generic_to_shared(As);
    uint32_t smW = (uint32_t)__cvta_generic_to_shared(Ws);

    stage_a64(smA, inI, ry0, CIRC, 0, KPH, tid, 512);
    for (int i = tid; i < WHALF; i += 512)
        cp16(smW + i * 16, wp + i * 4, 16);
    CP_COMMIT();
    stage_a64(smA, inI, ry0, CIRC, KPH, KP, tid, 512);
    for (int i = tid; i < WHALF; i += 512)
        cp16(smW + (WHALF + i) * 16, wp + (WHALF + i) * 4, 16);
    CP_COMMIT();

    float acc[2][8][4];
#pragma unroll
    for (int mt = 0; mt < 2; mt++)
#pragma unroll
        for (int g = 0; g < 8; g++)
#pragma unroll
            for (int j = 0; j < 4; j++) acc[mt][g][j] = 0.f;

    int mbase = (2 + row) * 72 + 4 + 32 * xhalf + qp;

    CP_WAIT1(); __syncthreads();
#pragma unroll
    for (int kh = 0; kh < 2; kh++) {
        if (kh) { CP_WAIT0(); __syncthreads(); }
#pragma unroll
        for (int kt = kh * (KT / 2); kt < (kh + 1) * (KT / 2); kt++) {
#pragma unroll
            for (int tap = 0; tap < 9; tap++) {
                int dy = tap / 3, dx = tap - dy * 3;
                int apos = mbase + (dy - 1 + vy) * 72 + (dx - 1 + vx);
                int wr = ((kt * 9 + tap) * 8 + qt) * 100 + qp * 12;
                uint4 L0 = *(const uint4*)(Ws + wr);
                uint4 L1 = *(const uint4*)(Ws + wr + 4);
                uint4 L2 = *(const uint4*)(Ws + wr + 4 * 100);
                uint4 L3 = *(const uint4*)(Ws + wr + 4 * 100 + 4);
                unsigned b0[8] = {L0.x, L0.y, L0.z, L0.w, L1.x, L1.y, L1.z, L1.w};
                unsigned b1[8] = {L2.x, L2.y, L2.z, L2.w, L3.x, L3.y, L3.z, L3.w};
                int ar0 = (kt * 8 + qt) * 872, ar2 = ar0 + 4 * 872;
#pragma unroll
                for (int mt = 0; mt < 2; mt++) {
                    int base = apos + mt * 16;
                    unsigned a0 = As[ar0 + base], a1 = As[ar0 + base + 8];
                    unsigned a2 = As[ar2 + base], a3 = As[ar2 + base + 8];
#pragma unroll
                    for (int g = 0; g < 8; g++)
                        mma16(acc[mt][g], a0, a1, a2, a3, b0[g], b1[g]);
                }
            }
        }
    }

    // ---- epilogue ----
    int y = ry0 + row;
#pragma unroll
    for (int mt = 0; mt < 2; mt++) {
        int x0 = 32 * xhalf + qp + mt * 16;
        int pixA = y * 64 + x0, pixB = pixA + 8;
#pragma unroll
        for (int g = 0; g < 8; g++) {
            int kp = g * 4 + qt, c = kp * 2;
            float v0 = acc[mt][g][0], v1 = acc[mt][g][1];
            float v2 = acc[mt][g][2], v3 = acc[mt][g][3];
            if (EPI == 0 || EPI == 1) {
                float s0 = gm[c] * BNS_C, s1 = gm[c+1] * BNS_C;
                float o0 = bt[c], o1 = bt[c+1];
                v0 = fmaxf(v0 * s0 + o0, 0.f); v1 = fmaxf(v1 * s1 + o1, 0.f);
                v2 = fmaxf(v2 * s0 + o0, 0.f); v3 = fmaxf(v3 * s1 + o1, 0.f);
                if (EPI == 0) {
                    unsigned* o = outH + ((size_t)img * 32 + kp) * PIX;
                    o[pixA] = packh(v0, v1); o[pixB] = packh(v2, v3);
                } else {
                    float2* o = (float2*)outF + ((size_t)img * 32 + kp) * PIX;
                    o[pixA] = make_float2(v0, v1); o[pixB] = make_float2(v2, v3);
                }
            } else {
                const float2* a = (const float2*)add +
                    ((size_t)(tstep * 4 + img / NV) * 32 + kp) * PIX;
                float2 xa = a[pixA], xb = a[pixB];
                float t0 = tanh_ap(v0 + xa.x), t1 = tanh_ap(v1 + xa.y);
                float t2 = tanh_ap(v2 + xb.x), t3 = tanh_ap(v3 + xb.y);
                unsigned* o = outH + ((size_t)img * 32 + kp) * PIX;
                o[pixA] = packh(t0, t1); o[pixB] = packh(t2, t3);
            }
        }
    }
}

// ---------------- fused up+h1 kernel -----------------------------------------
// Phase 1: conv_ul(h0new) zero-pad -> bn/relu -> up (local fp32).
// Phase 2: conv_h1(h1old) circular+velocity -> tanh(acc + up) -> h1 + d_out.
__global__ void __launch_bounds__(512, 1)
convfuse_k(const unsigned* __restrict__ h0new, const unsigned* __restrict__ h1old,
           const unsigned* __restrict__ wpul, const unsigned* __restrict__ wph1,
           const float* __restrict__ gul, const float* __restrict__ bul,
           unsigned* __restrict__ h1out, float* __restrict__ dout, int tstep) {
    extern __shared__ unsigned smu[];
    unsigned* As = smu;                  // [32][872]
    unsigned* Ws = smu + 32 * 872;       // [288 rows][100]

    int img = blockIdx.y, ry0 = blockIdx.x * 8;
    int tid = threadIdx.x;
    int w = tid >> 5, qp = (tid >> 2) & 7, qt = tid & 3;
    int row = w >> 1, xhalf = w & 1;
    int v = img % NV, vy = v / 3 - 1, vx = v % 3 - 1;
    uint32_t smA = (uint32_t)__cvta_generic_to_shared(As);
    uint32_t smW = (uint32_t)__cvta_generic_to_shared(Ws);
    int mbase = (2 + row) * 72 + 4 + 32 * xhalf + qp;

    // ---- phase 1: conv_ul on h0new (zero pad, no shift) ----
    {
        const unsigned* inI = h0new + (size_t)img * 32 * PIX;
        stage_a64(smA, inI, ry0, false, 0, 32, tid, 512);
        for (int i = tid; i < 7200; i += 512)
            cp16(smW + i * 16, wpul + i * 4, 16);
        CP_COMMIT(); CP_WAIT0(); __syncthreads();
    }
    float acc[2][8][4];
#pragma unroll
    for (int mt = 0; mt < 2; mt++)
#pragma unroll
        for (int g = 0; g < 8; g++)
#pragma unroll
            for (int j = 0; j < 4; j++) acc[mt][g][j] = 0.f;
    mainloop64(As, Ws, mbase, 0, 0, qt, qp, acc);

    // bn/relu -> up local array (fp32; L1-resident local; intended)
    float upl[64];
#pragma unroll
    for (int mt = 0; mt < 2; mt++)
#pragma unroll
        for (int g = 0; g < 8; g++) {
            int c = (g * 4 + qt) * 2;
            float s0 = gul[c] * BNS_C, s1 = gul[c + 1] * BNS_C;
            float o0 = bul[c], o1 = bul[c + 1];
            upl[mt * 32 + g * 4 + 0] = fmaxf(acc[mt][g][0] * s0 + o0, 0.f);
            upl[mt * 32 + g * 4 + 1] = fmaxf(acc[mt][g][1] * s1 + o1, 0.f);
            upl[mt * 32 + g * 4 + 2] = fmaxf(acc[mt][g][2] * s0 + o0, 0.f);
            upl[mt * 32 + g * 4 + 3] = fmaxf(acc[mt][g][3] * s1 + o1, 0.f);
        }
    __syncthreads();     // all warps done reading As/Ws

    // ---- phase 2: conv_h1 on h1old (circular + velocity shift) ----
    {
        const unsigned* inI = h1old + (size_t)img * 32 * PIX;
        stage_a64(smA, inI, ry0, true, 0, 32, tid, 512);
        for (int i = tid; i < 7200; i += 512)
            cp16(smW + i * 16, wph1 + i * 4, 16);
        CP_COMMIT(); CP_WAIT0(); __syncthreads();
    }
#pragma unroll
    for (int mt = 0; mt < 2; mt++)
#pragma unroll
        for (int g = 0; g < 8; g++)
#pragma unroll
            for (int j = 0; j < 4; j++) acc[mt][g][j] = 0.f;
    mainloop64(As, Ws, mbase, vy, vx, qt, qp, acc);

    // ---- epilogue: h1 = tanh(acc + up); write h1 half2 + d_out fp32 ----
    int y = ry0 + row;
    int v9 = img % NV, bb = img / NV;
#pragma unroll
    for (int mt = 0; mt < 2; mt++) {
        int x0 = 32 * xhalf + qp + mt * 16;
        int pixA = y * 64 + x0, pixB = pixA + 8;
#pragma unroll
        for (int g = 0; g < 8; g++) {
            int kp = g * 4 + qt, c = kp * 2;
            float t0 = tanh_ap(acc[mt][g][0] + upl[mt * 32 + g * 4 + 0]);
            float t1 = tanh_ap(acc[mt][g][1] + upl[mt * 32 + g * 4 + 1]);
            float t2 = tanh_ap(acc[mt][g][2] + upl[mt * 32 + g * 4 + 2]);
            float t3 = tanh_ap(acc[mt][g][3] + upl[mt * 32 + g * 4 + 3]);
            unsigned* o = h1out + ((size_t)img * 32 + kp) * PIX;
            o[pixA] = packh(t0, t1); o[pixB] = packh(t2, t3);
            float* q = dout + (((size_t)(v9 * 4 + bb) * 64 + c) * 8 + tstep) * PIX;
            q[pixA] = t0; q[pixB] = t2;
            q += 8 * PIX;
            q[pixA] = t1; q[pixB] = t3;
        }
    }
}

// ---------------- host driver -------------------------------------------------
extern "C" void kernel_launch(void* const* d_in, const int* in_sizes, int n_in,
                              void* d_out, int out_size) {
    (void)in_sizes; (void)n_in; (void)out_size;
    const float* u   = (const float*)d_in[0];
    const float* w1  = (const float*)d_in[1];
    const float* g1  = (const float*)d_in[2];
    const float* b1  = (const float*)d_in[3];
    const float* w2  = (const float*)d_in[4];
    const float* g2  = (const float*)d_in[5];
    const float* b2  = (const float*)d_in[6];
    const float* w3  = (const float*)d_in[7];
    const float* g3  = (const float*)d_in[8];
    const float* b3  = (const float*)d_in[9];
    const float* wul = (const float*)d_in[10];
    const float* gul = (const float*)d_in[11];
    const float* bul = (const float*)d_in[12];
    const float* wh0 = (const float*)d_in[13];
    const float* wh1 = (const float*)d_in[14];
    float* out = (float*)d_out;

    const int SM64B = (32 * 872 + 288 * 100) * 4;   // 226816
    const int SM32B = (16 * 872 + 144 * 100) * 4;   // 113408

    static unsigned *pe1 = nullptr, *pe2, *ph0, *ph1,
                    *pw2, *pw3, *pwul, *pwh0, *pwh1;
    static float *px, *pup;
    if (!pe1) {   // pointer caching + attrs; runs on the pre-capture call
        cudaGetSymbolAddress((void**)&pe1,  g_e1);
        cudaGetSymbolAddress((void**)&pe2,  g_e2);
        cudaGetSymbolAddress((void**)&ph0,  g_h0);
        cudaGetSymbolAddress((void**)&ph1,  g_h1);
        cudaGetSymbolAddress((void**)&px,   g_x);
        cudaGetSymbolAddress((void**)&pup,  g_up);
        cudaGetSymbolAddress((void**)&pw2,  g_wp2);
        cudaGetSymbolAddress((void**)&pw3,  g_wp3);
        cudaGetSymbolAddress((void**)&pwul, g_wpul);
        cudaGetSymbolAddress((void**)&pwh0, g_wph0);
        cudaGetSymbolAddress((void**)&pwh1, g_wph1);
        cudaFuncSetAttribute(convh_k<32, false, 0>,
                             cudaFuncAttributeMaxDynamicSharedMemorySize, SM32B);
        cudaFuncSetAttribute(convh_k<64, false, 1>,
                             cudaFuncAttributeMaxDynamicSharedMemorySize, SM64B);
        cudaFuncSetAttribute(convh_k<64, true, 2>,
                             cudaFuncAttributeMaxDynamicSharedMemorySize, SM64B);
        cudaFuncSetAttribute(convfuse_k,
                             cudaFuncAttributeMaxDynamicSharedMemorySize, SM64B);
    }
    const size_t HSZ = 36ull * 32 * PIX;   // h buffer parity size (u32 units)

    prep_w_k<<<dim3(72, 5), 256>>>(w2, w3, wul, wh0, wh1);

    // encoder
    conv1q_k<<<dim3(4, 32), 256>>>(u, w1, g1, b1, pe1);
    convh_k<32, false, 0><<<dim3(8, 32), 512, SM32B>>>(
        pe1, pw2, g2, b2, nullptr, pe2, nullptr, 0, 1);
    convh_k<64, false, 1><<<dim3(8, 32), 512, SM64B>>>(
        pe2, pw3, g3, b3, nullptr, nullptr, px, 0, 1);

    // ---- t = 0 (hidden states zero): algebraic shortcut ----
    h0t0_k<<<dim3(512, 4), 256>>>(px, ph0 + HSZ);                 // parity 1
    convh_k<64, false, 1><<<dim3(8, 4), 512, SM64B>>>(            // up_0, 4 imgs
        ph0 + HSZ, pwul, gul, bul, nullptr, nullptr, pup, 0, 9);
    h1t0_k<<<dim3(512, 4), 256>>>(pup, ph1 + HSZ, out);           // parity 1

    // ---- recurrent steps t = 1..7 ----
    for (int t = 1; t < 8; t++) {
        int rp = t & 1, wpp = 1 - rp;
        // h0 = tanh(x_t + circ-shift conv(h0_old, w_h0))
        convh_k<64, true, 2><<<dim3(8, 36), 512, SM64B>>>(
            ph0 + rp * HSZ, pwh0, nullptr, nullptr, px,
            ph0 + wpp * HSZ, nullptr, t, 1);
        // fused: up = relu(bn(conv_ul(h0_new))); h1 = tanh(up + conv_h1(h1_old))
        convfuse_k<<<dim3(8, 36), 512, SM64B>>>(
            ph0 + wpp * HSZ, ph1 + rp * HSZ, pwul, pwh1,
            gul, bul, ph1 + wpp * HSZ, out, t);
    }
}

// round 15
// speedup vs baseline: 1.1598x; 1.0308x over previous
#include <cuda_runtime.h>
#include <cuda_fp16.h>
#include <math.h>
#include <stdint.h>

#define PIX 4096
#define NV 9

// ---------------- scratch (device globals; half2 feature buffers) ------------
__device__ unsigned g_e1[32ull*16*PIX];     // encoder stage1, 32ch = 16 kpairs
__device__ unsigned g_e2[32ull*32*PIX];     // encoder stage2, 64ch = 32 kpairs
__device__ unsigned g_h0[2ull*36*32*PIX];   // ping-pong h0 (half2)
__device__ unsigned g_h1[2ull*36*32*PIX];   // ping-pong h1 (half2)
__device__ float    g_x [32ull*32*PIX*2];   // fp32 addend x, float2-interleaved
__device__ float    g_up[36ull*32*PIX*2];   // fp32 addend up (t=0 path only)
// pre-permuted half2 weights, kt-major conflict-free image (row stride 100 u32)
__device__ unsigned g_wp2 [144*100];
__device__ unsigned g_wp3 [288*100];
__device__ unsigned g_wpul[288*100];
__device__ unsigned g_wph0[288*100];
__device__ unsigned g_wph1[288*100];

// ---------------- helpers -----------------------------------------------------
__device__ __forceinline__ void cp16(uint32_t s, const void* g, int srcsz) {
    asm volatile("cp.async.cg.shared.global [%0], [%1], 16, %2;"
                 :: "r"(s), "l"(g), "r"(srcsz));
}
__device__ __forceinline__ void cp8(uint32_t s, const void* g, int srcsz) {
    asm volatile("cp.async.ca.shared.global [%0], [%1], 8, %2;"
                 :: "r"(s), "l"(g), "r"(srcsz));
}
#define CP_COMMIT() asm volatile("cp.async.commit_group;")
#define CP_WAIT1()  asm volatile("cp.async.wait_group 1;" ::: "memory")
#define CP_WAIT0()  asm volatile("cp.async.wait_group 0;" ::: "memory")

__device__ __forceinline__ void mma16(float* d, unsigned a0, unsigned a1,
                                      unsigned a2, unsigned a3,
                                      unsigned b0, unsigned b1) {
    asm("mma.sync.aligned.m16n8k16.row.col.f32.f16.f16.f32 "
        "{%0,%1,%2,%3},{%4,%5,%6,%7},{%8,%9},{%0,%1,%2,%3};"
        : "+f"(d[0]), "+f"(d[1]), "+f"(d[2]), "+f"(d[3])
        : "r"(a0), "r"(a1), "r"(a2), "r"(a3), "r"(b0), "r"(b1));
}
__device__ __forceinline__ unsigned packh(float a, float b) {
    __half2 h = __halves2half2(__float2half_rn(a), __float2half_rn(b));
    return *(unsigned*)&h;
}
__device__ __forceinline__ float tanh_ap(float x) {
    float r;
    asm("tanh.approx.f32 %0, %1;" : "=f"(r) : "f"(x));
    return r;
}
__device__ __forceinline__ unsigned long long ffma2(unsigned long long a,
                                                    unsigned long long b,
                                                    unsigned long long c) {
    unsigned long long d;
    asm("fma.rn.f32x2 %0, %1, %2, %3;" : "=l"(d) : "l"(a), "l"(b), "l"(c));
    return d;
}
__device__ __forceinline__ unsigned long long pack_dup(float v) {
    unsigned long long d; unsigned r = __float_as_uint(v);
    asm("mov.b64 %0, {%1, %1};" : "=l"(d) : "r"(r));
    return d;
}
__device__ __forceinline__ void unpack2(unsigned long long v, float& lo, float& hi) {
    unsigned a, b;
    asm("mov.b64 {%0, %1}, %2;" : "=r"(a), "=r"(b) : "l"(v));
    lo = __uint_as_float(a); hi = __uint_as_float(b);
}
__constant__ float BNS_C = 0.9999950000374996f;   // 1/sqrt(1+1e-5)

// weights -> half2, kt-major: row = (kt*9+tap)*8+kp8 (stride 100), col gid*12+g
__global__ void prep_w_k(const float* __restrict__ w2, const float* __restrict__ w3,
                         const float* __restrict__ wul, const float* __restrict__ wh0,
                         const float* __restrict__ wh1) {
    int idx = blockIdx.x * 256 + threadIdx.x, conv = blockIdx.y;
    const float* src; unsigned* dst; int CIN;
    if      (conv == 0) { src = w2;  dst = g_wp2;  CIN = 32; }
    else if (conv == 1) { src = w3;  dst = g_wp3;  CIN = 64; }
    else if (conv == 2) { src = wul; dst = g_wpul; CIN = 64; }
    else if (conv == 3) { src = wh0; dst = g_wph0; CIN = 64; }
    else                { src = wh1; dst = g_wph1; CIN = 64; }
    int KP = CIN >> 1;
    if (idx >= 9 * KP * 64) return;
    int tap = idx / (KP * 64), rem = idx - tap * (KP * 64);
    int kp = rem >> 6, n = rem & 63;
    int kt = kp >> 3, kp8 = kp & 7, gid = n & 7, g = n >> 3;
    float lo = src[((size_t)n * CIN + 2 * kp) * 9 + tap];
    float hi = src[((size_t)n * CIN + 2 * kp + 1) * 9 + tap];
    dst[((kt * 9 + tap) * 8 + kp8) * 100 + gid * 12 + g] = packh(lo, hi);
}

// ---------------- encoder conv1: 3->32, 5x5, quad-tiled f32x2 ----------------
__global__ void __launch_bounds__(256, 1)
conv1q_k(const float* __restrict__ u, const float* __restrict__ wt,
         const float* __restrict__ gm, const float* __restrict__ bt,
         unsigned* __restrict__ out) {
    __shared__ float sIn[3][1296];    // 3 x 36x36 (halo 2)
    __shared__ float sW[2400];        // [cin][tap25][cout32]
    int tile = blockIdx.x, e = blockIdx.y;      // e = t*4+b
    int tstep = e >> 2, bb = e & 3;
    int ty0 = (tile >> 1) << 5, tx0 = (tile & 1) << 5;
    int tid = threadIdx.x, lx = tid & 15, ly = tid >> 4;
    int qy = ly << 1, qx = lx << 1;
    const float* inI = u + (size_t)(bb * 8 + tstep) * 3 * PIX;
    for (int i = tid; i < 2400; i += 256) {
        int k = i / 800, r = i - k * 800, t5 = r >> 5, c = r & 31;
        sW[i] = wt[(c * 3 + k) * 25 + t5];
    }
    for (int i = tid; i < 3 * 1296; i += 256) {
        int k = i / 1296, rem = i - k * 1296, ry = rem / 36, rx = rem - ry * 36;
        int gy = ty0 + ry - 2, gx = tx0 + rx - 2;
        sIn[k][rem] = (gy >= 0 && gy < 64 && gx >= 0 && gx < 64)
                      ? inI[(size_t)k * PIX + gy * 64 + gx] : 0.f;
    }
    __syncthreads();

    unsigned long long acc[16][4];
#pragma unroll
    for (int p = 0; p < 16; p++)
#pragma unroll
        for (int j = 0; j < 4; j++) acc[p][j] = 0ull;

    for (int k = 0; k < 3; k++) {
        unsigned long long n2[36];
#pragma unroll
        for (int dy = 0; dy < 6; dy++)
#pragma unroll
            for (int dx = 0; dx < 6; dx++)
                n2[dy * 6 + dx] = pack_dup(sIn[k][(qy + dy) * 36 + qx + dx]);
#pragma unroll
        for (int t5 = 0; t5 < 25; t5++) {
            int dy = t5 / 5, dx = t5 - dy * 5;
            const unsigned long long* w2p =
                (const unsigned long long*)(sW + k * 800 + t5 * 32);
#pragma unroll
            for (int p = 0; p < 16; p++) {
                unsigned long long w = w2p[p];
#pragma unroll
                for (int py = 0; py < 2; py++)
#pragma unroll
                    for (int pxx = 0; pxx < 2; pxx++)
                        acc[p][py * 2 + pxx] =
                            ffma2(w, n2[(py + dy) * 6 + (pxx + dx)], acc[p][py * 2 + pxx]);
            }
        }
    }
    unsigned* o = out + (size_t)e * 16 * PIX;
#pragma unroll
    for (int p = 0; p < 16; p++) {
        int c = 2 * p;
        float s0 = gm[c] * BNS_C, o0 = bt[c];
        float s1 = gm[c + 1] * BNS_C, o1 = bt[c + 1];
#pragma unroll
        for (int py = 0; py < 2; py++)
#pragma unroll
            for (int pxx = 0; pxx < 2; pxx++) {
                float lo, hi;
                unpack2(acc[p][py * 2 + pxx], lo, hi);
                float r0 = fmaxf(lo * s0 + o0, 0.f), r1 = fmaxf(hi * s1 + o1, 0.f);
                o[(size_t)p * PIX + (ty0 + qy + py) * 64 + tx0 + qx + pxx] = packh(r0, r1);
            }
    }
}

// ---------------- t=0 shortcuts ----------------------------------------------
__global__ void h0t0_k(const float* __restrict__ x, unsigned* __restrict__ h0) {
    int b = blockIdx.y;
    int i = blockIdx.x * 256 + threadIdx.x;          // < 32*PIX
    float2 xv = ((const float2*)x)[(size_t)b * 32 * PIX + i];
    unsigned hv = packh(tanh_ap(xv.x), tanh_ap(xv.y));
#pragma unroll
    for (int v = 0; v < 9; v++)
        h0[((size_t)(b * 9 + v) * 32) * PIX + i] = hv;
}
__global__ void h1t0_k(const float* __restrict__ up, unsigned* __restrict__ h1,
                       float* __restrict__ dout) {
    int b = blockIdx.y;
    int i = blockIdx.x * 256 + threadIdx.x;          // kp*PIX + pix
    int kp = i >> 12, pix = i & 4095, c = kp * 2;
    float2 uv = ((const float2*)up)[((size_t)(b * 9) * 32 + kp) * PIX + pix];
    float t0 = tanh_ap(uv.x), t1 = tanh_ap(uv.y);
    unsigned hv = packh(t0, t1);
#pragma unroll
    for (int v = 0; v < 9; v++) {
        h1[((size_t)(b * 9 + v) * 32 + kp) * PIX + pix] = hv;
        float* q = dout + (((size_t)(v * 4 + b) * 64 + c) * 8) * PIX;
        q[pix] = t0; q[8 * PIX + pix] = t1;
    }
}

// ---------------- shared staging for 64-cin convs (KP=32) --------------------
__device__ __forceinline__ void stage_a64(uint32_t smA, const unsigned* inI,
                                          int ry0, bool circ, int k0, int k1,
                                          int tid, int nthr) {
    for (int i = k0 * 216 + tid; i < k1 * 216; i += nthr) {
        int k = i / 216, rem = i % 216, r = rem / 18, s = rem - r * 18;
        int gy = ry0 + r - 2;
        bool rowok = true;
        if (circ) gy &= 63; else rowok = (gy >= 0 && gy < 64);
        const unsigned* srow = inI + (size_t)k * PIX + gy * 64;
        uint32_t dst = smA + (uint32_t)(k * 872 + r * 72) * 4u;
        if (s < 16)       cp16(dst + (4 + s * 4) * 4, srow + s * 4, rowok ? 16 : 0);
        else if (s == 16) cp8(dst + 2 * 4, srow + 62, (circ && rowok) ? 8 : 0);
        else              cp8(dst + 68 * 4, srow,     (circ && rowok) ? 8 : 0);
    }
}

// mainloop for one 64-cin conv (KT=4); acc += conv
__device__ __forceinline__ void mainloop64(const unsigned* As, const unsigned* Ws,
                                           int mbase, int vy, int vx,
                                           int qt, int qp, float acc[2][8][4]) {
#pragma unroll
    for (int kt = 0; kt < 4; kt++) {
#pragma unroll
        for (int tap = 0; tap < 9; tap++) {
            int dy = tap / 3, dx = tap - dy * 3;
            int apos = mbase + (dy - 1 + vy) * 72 + (dx - 1 + vx);
            int wr = ((kt * 9 + tap) * 8 + qt) * 100 + qp * 12;
            uint4 L0 = *(const uint4*)(Ws + wr);
            uint4 L1 = *(const uint4*)(Ws + wr + 4);
            uint4 L2 = *(const uint4*)(Ws + wr + 4 * 100);
            uint4 L3 = *(const uint4*)(Ws + wr + 4 * 100 + 4);
            unsigned b0[8] = {L0.x, L0.y, L0.z, L0.w, L1.x, L1.y, L1.z, L1.w};
            unsigned b1[8] = {L2.x, L2.y, L2.z, L2.w, L3.x, L3.y, L3.z, L3.w};
            int ar0 = (kt * 8 + qt) * 872, ar2 = ar0 + 4 * 872;
#pragma unroll
            for (int mt = 0; mt < 2; mt++) {
                int base = apos + mt * 16;
                unsigned a0 = As[ar0 + base], a1 = As[ar0 + base + 8];
                unsigned a2 = As[ar2 + base], a3 = As[ar2 + base + 8];
#pragma unroll
                for (int g = 0; g < 8; g++)
                    mma16(acc[mt][g], a0, a1, a2, a3, b0[g], b1[g]);
            }
        }
    }
}

// ---------------- fp16 tensor-core 3x3 conv, CIN->64 (R9 config) -------------
// Block 512 thr = 16 warps; 8 output rows x 64 px; warp = (row 0..7, xhalf).
// EPI 0: BN+ReLU -> half2    EPI 1: BN+ReLU -> float2 addend
// EPI 2: tanh(acc + x) -> half2
template <int CIN, bool CIRC, int EPI>
__global__ void __launch_bounds__(512, 1)
convh_k(const unsigned* __restrict__ in, const unsigned* __restrict__ wp,
        const float* __restrict__ gm, const float* __restrict__ bt,
        const float* __restrict__ add, unsigned* __restrict__ outH,
        float* __restrict__ outF, int tstep, int imgstep) {
    constexpr int KP = CIN / 2, KT = CIN / 16, KPH = KP / 2;
    constexpr int WHALF = (KT / 2) * 9 * 8 * 25;     // uint4 per W half
    extern __shared__ unsigned smu[];
    unsigned* As = smu;                  // [KP][872]
    unsigned* Ws = smu + KP * 872;       // [KT*9*8 rows][100]

    int img = blockIdx.y * imgstep, ry0 = blockIdx.x * 8;
    int tid = threadIdx.x;
    int w = tid >> 5, qp = (tid >> 2) & 7, qt = tid & 3;
    int row = w >> 1, xhalf = w & 1;
    int vy = 0, vx = 0;
    if (CIRC) { int v = img % NV; vy = v / 3 - 1; vx = v % 3 - 1; }
    const unsigned* inI = in + (size_t)img * KP * PIX;
    uint32_t smA = (uint32_t)__cvta_generic_to_shared(As);
    uint32_t smW = (uint32_t)__cvta_generic_to_shared(Ws);

    stage_a64(smA, inI, ry0, CIRC, 0, KPH, tid, 512);
    for (int i = tid; i < WHALF; i += 512)
        cp16(smW + i * 16, wp + i * 4, 16);
    CP_COMMIT();
    stage_a64(smA, inI, ry0, CIRC, KPH, KP, tid, 512);
    for (int i = tid; i < WHALF; i += 512)
        cp16(smW + (WHALF + i) * 16, wp + (WHALF + i) * 4, 16);
    CP_COMMIT();

    float acc[2][8][4];
#pragma unroll
    for (int mt = 0; mt < 2; mt++)
#pragma unroll
        for (int g = 0; g < 8; g++)
#pragma unroll
            for (int j = 0; j < 4; j++) acc[mt][g][j] = 0.f;

    int mbase = (2 + row) * 72 + 4 + 32 * xhalf + qp;

    CP_WAIT1(); __syncthreads();
#pragma unroll
    for (int kh = 0; kh < 2; kh++) {
        if (kh) { CP_WAIT0(); __syncthreads(); }
#pragma unroll
        for (int kt = kh * (KT / 2); kt < (kh + 1) * (KT / 2); kt++) {
#pragma unroll
            for (int tap = 0; tap < 9; tap++) {
                int dy = tap / 3, dx = tap - dy * 3;
                int apos = mbase + (dy - 1 + vy) * 72 + (dx - 1 + vx);
                int wr = ((kt * 9 + tap) * 8 + qt) * 100 + qp * 12;
                uint4 L0 = *(const uint4*)(Ws + wr);
                uint4 L1 = *(const uint4*)(Ws + wr + 4);
                uint4 L2 = *(const uint4*)(Ws + wr + 4 * 100);
                uint4 L3 = *(const uint4*)(Ws + wr + 4 * 100 + 4);
                unsigned b0[8] = {L0.x, L0.y, L0.z, L0.w, L1.x, L1.y, L1.z, L1.w};
                unsigned b1[8] = {L2.x, L2.y, L2.z, L2.w, L3.x, L3.y, L3.z, L3.w};
                int ar0 = (kt * 8 + qt) * 872, ar2 = ar0 + 4 * 872;
#pragma unroll
                for (int mt = 0; mt < 2; mt++) {
                    int base = apos + mt * 16;
                    unsigned a0 = As[ar0 + base], a1 = As[ar0 + base + 8];
                    unsigned a2 = As[ar2 + base], a3 = As[ar2 + base + 8];
#pragma unroll
                    for (int g = 0; g < 8; g++)
                        mma16(acc[mt][g], a0, a1, a2, a3, b0[g], b1[g]);
                }
            }
        }
    }

    // ---- epilogue ----
    int y = ry0 + row;
#pragma unroll
    for (int mt = 0; mt < 2; mt++) {
        int x0 = 32 * xhalf + qp + mt * 16;
        int pixA = y * 64 + x0, pixB = pixA + 8;
#pragma unroll
        for (int g = 0; g < 8; g++) {
            int kp = g * 4 + qt, c = kp * 2;
            float v0 = acc[mt][g][0], v1 = acc[mt][g][1];
            float v2 = acc[mt][g][2], v3 = acc[mt][g][3];
            if (EPI == 0 || EPI == 1) {
                float s0 = gm[c] * BNS_C, s1 = gm[c+1] * BNS_C;
                float o0 = bt[c], o1 = bt[c+1];
                v0 = fmaxf(v0 * s0 + o0, 0.f); v1 = fmaxf(v1 * s1 + o1, 0.f);
                v2 = fmaxf(v2 * s0 + o0, 0.f); v3 = fmaxf(v3 * s1 + o1, 0.f);
                if (EPI == 0) {
                    unsigned* o = outH + ((size_t)img * 32 + kp) * PIX;
                    o[pixA] = packh(v0, v1); o[pixB] = packh(v2, v3);
                } else {
                    float2* o = (float2*)outF + ((size_t)img * 32 + kp) * PIX;
                    o[pixA] = make_float2(v0, v1); o[pixB] = make_float2(v2, v3);
                }
            } else {
                const float2* a = (const float2*)add +
                    ((size_t)(tstep * 4 + img / NV) * 32 + kp) * PIX;
                float2 xa = a[pixA], xb = a[pixB];
                float t0 = tanh_ap(v0 + xa.x), t1 = tanh_ap(v1 + xa.y);
                float t2 = tanh_ap(v2 + xb.x), t3 = tanh_ap(v3 + xb.y);
                unsigned* o = outH + ((size_t)img * 32 + kp) * PIX;
                o[pixA] = packh(t0, t1); o[pixB] = packh(t2, t3);
            }
        }
    }
}

// ---------------- fused up+h1 kernel -----------------------------------------
__global__ void __launch_bounds__(512, 1)
convfuse_k(const unsigned* __restrict__ h0new, const unsigned* __restrict__ h1old,
           const unsigned* __restrict__ wpul, const unsigned* __restrict__ wph1,
           const float* __restrict__ gul, const float* __restrict__ bul,
           unsigned* __restrict__ h1out, float* __restrict__ dout, int tstep) {
    extern __shared__ unsigned smu[];
    unsigned* As = smu;                  // [32][872]
    unsigned* Ws = smu + 32 * 872;       // [288 rows][100]

    int img = blockIdx.y, ry0 = blockIdx.x * 8;
    int tid = threadIdx.x;
    int w = tid >> 5, qp = (tid >> 2) & 7, qt = tid & 3;
    int row = w >> 1, xhalf = w & 1;
    int v = img % NV, vy = v / 3 - 1, vx = v % 3 - 1;
    uint32_t smA = (uint32_t)__cvta_generic_to_shared(As);
    uint32_t smW = (uint32_t)__cvta_generic_to_shared(Ws);
    int mbase = (2 + row) * 72 + 4 + 32 * xhalf + qp;

    // ---- phase 1: conv_ul on h0new (zero pad, no shift) ----
    {
        const unsigned* inI = h0new + (size_t)img * 32 * PIX;
        stage_a64(smA, inI, ry0, false, 0, 32, tid, 512);
        for (int i = tid; i < 7200; i += 512)
            cp16(smW + i * 16, wpul + i * 4, 16);
        CP_COMMIT(); CP_WAIT0(); __syncthreads();
    }
    float acc[2][8][4];
#pragma unroll
    for (int mt = 0; mt < 2; mt++)
#pragma unroll
        for (int g = 0; g < 8; g++)
#pragma unroll
            for (int j = 0; j < 4; j++) acc[mt][g][j] = 0.f;
    mainloop64(As, Ws, mbase, 0, 0, qt, qp, acc);

    // bn/relu -> up local array (fp32; L1-resident local; intended)
    float upl[64];
#pragma unroll
    for (int mt = 0; mt < 2; mt++)
#pragma unroll
        for (int g = 0; g < 8; g++) {
            int c = (g * 4 + qt) * 2;
            float s0 = gul[c] * BNS_C, s1 = gul[c + 1] * BNS_C;
            float o0 = bul[c], o1 = bul[c + 1];
            upl[mt * 32 + g * 4 + 0] = fmaxf(acc[mt][g][0] * s0 + o0, 0.f);
            upl[mt * 32 + g * 4 + 1] = fmaxf(acc[mt][g][1] * s1 + o1, 0.f);
            upl[mt * 32 + g * 4 + 2] = fmaxf(acc[mt][g][2] * s0 + o0, 0.f);
            upl[mt * 32 + g * 4 + 3] = fmaxf(acc[mt][g][3] * s1 + o1, 0.f);
        }
    __syncthreads();     // all warps done reading As/Ws

    // ---- phase 2: conv_h1 on h1old (circular + velocity shift) ----
    {
        const unsigned* inI = h1old + (size_t)img * 32 * PIX;
        stage_a64(smA, inI, ry0, true, 0, 32, tid, 512);
        for (int i = tid; i < 7200; i += 512)
            cp16(smW + i * 16, wph1 + i * 4, 16);
        CP_COMMIT(); CP_WAIT0(); __syncthreads();
    }
#pragma unroll
    for (int mt = 0; mt < 2; mt++)
#pragma unroll
        for (int g = 0; g < 8; g++)
#pragma unroll
            for (int j = 0; j < 4; j++) acc[mt][g][j] = 0.f;
    mainloop64(As, Ws, mbase, vy, vx, qt, qp, acc);

    // ---- epilogue: h1 = tanh(acc + up); write h1 half2 + d_out fp32 ----
    int y = ry0 + row;
    int v9 = img % NV, bb = img / NV;
#pragma unroll
    for (int mt = 0; mt < 2; mt++) {
        int x0 = 32 * xhalf + qp + mt * 16;
        int pixA = y * 64 + x0, pixB = pixA + 8;
#pragma unroll
        for (int g = 0; g < 8; g++) {
            int kp = g * 4 + qt, c = kp * 2;
            float t0 = tanh_ap(acc[mt][g][0] + upl[mt * 32 + g * 4 + 0]);
            float t1 = tanh_ap(acc[mt][g][1] + upl[mt * 32 + g * 4 + 1]);
            float t2 = tanh_ap(acc[mt][g][2] + upl[mt * 32 + g * 4 + 2]);
            float t3 = tanh_ap(acc[mt][g][3] + upl[mt * 32 + g * 4 + 3]);
            unsigned* o = h1out + ((size_t)img * 32 + kp) * PIX;
            o[pixA] = packh(t0, t1); o[pixB] = packh(t2, t3);
            float* q = dout + (((size_t)(v9 * 4 + bb) * 64 + c) * 8 + tstep) * PIX;
            q[pixA] = t0; q[pixB] = t2;
            q += 8 * PIX;
            q[pixA] = t1; q[pixB] = t3;
        }
    }
}

// ---------------- host driver -------------------------------------------------
extern "C" void kernel_launch(void* const* d_in, const int* in_sizes, int n_in,
                              void* d_out, int out_size) {
    (void)in_sizes; (void)n_in; (void)out_size;
    const float* u   = (const float*)d_in[0];
    const float* w1  = (const float*)d_in[1];
    const float* g1  = (const float*)d_in[2];
    const float* b1  = (const float*)d_in[3];
    const float* w2  = (const float*)d_in[4];
    const float* g2  = (const float*)d_in[5];
    const float* b2  = (const float*)d_in[6];
    const float* w3  = (const float*)d_in[7];
    const float* g3  = (const float*)d_in[8];
    const float* b3  = (const float*)d_in[9];
    const float* wul = (const float*)d_in[10];
    const float* gul = (const float*)d_in[11];
    const float* bul = (const float*)d_in[12];
    const float* wh0 = (const float*)d_in[13];
    const float* wh1 = (const float*)d_in[14];
    float* out = (float*)d_out;

    const int SM64B = (32 * 872 + 288 * 100) * 4;   // 226816
    const int SM32B = (16 * 872 + 144 * 100) * 4;   // 113408

    static unsigned *pe1 = nullptr, *pe2, *ph0, *ph1,
                    *pw2, *pw3, *pwul, *pwh0, *pwh1;
    static float *px, *pup;
    static cudaStream_t sA = nullptr, sB = nullptr;
    static cudaEvent_t ev[24];
    if (!pe1) {   // pointer/stream/event setup; runs on the pre-capture call
        cudaGetSymbolAddress((void**)&pe1,  g_e1);
        cudaGetSymbolAddress((void**)&pe2,  g_e2);
        cudaGetSymbolAddress((void**)&ph0,  g_h0);
        cudaGetSymbolAddress((void**)&ph1,  g_h1);
        cudaGetSymbolAddress((void**)&px,   g_x);
        cudaGetSymbolAddress((void**)&pup,  g_up);
        cudaGetSymbolAddress((void**)&pw2,  g_wp2);
        cudaGetSymbolAddress((void**)&pw3,  g_wp3);
        cudaGetSymbolAddress((void**)&pwul, g_wpul);
        cudaGetSymbolAddress((void**)&pwh0, g_wph0);
        cudaGetSymbolAddress((void**)&pwh1, g_wph1);
        cudaFuncSetAttribute(convh_k<32, false, 0>,
                             cudaFuncAttributeMaxDynamicSharedMemorySize, SM32B);
        cudaFuncSetAttribute(convh_k<64, false, 1>,
                             cudaFuncAttributeMaxDynamicSharedMemorySize, SM64B);
        cudaFuncSetAttribute(convh_k<64, true, 2>,
                             cudaFuncAttributeMaxDynamicSharedMemorySize, SM64B);
        cudaFuncSetAttribute(convfuse_k,
                             cudaFuncAttributeMaxDynamicSharedMemorySize, SM64B);
        cudaStreamCreateWithFlags(&sA, cudaStreamNonBlocking);
        cudaStreamCreateWithFlags(&sB, cudaStreamNonBlocking);
        for (int i = 0; i < 24; i++)
            cudaEventCreateWithFlags(&ev[i], cudaEventDisableTiming);
    }
    const size_t HSZ = 36ull * 32 * PIX;   // h buffer parity size (u32 units)

    // ---- serial prefix on the captured (default) stream ----
    prep_w_k<<<dim3(72, 5), 256>>>(w2, w3, wul, wh0, wh1);
    conv1q_k<<<dim3(4, 32), 256>>>(u, w1, g1, b1, pe1);
    convh_k<32, false, 0><<<dim3(8, 32), 512, SM32B>>>(
        pe1, pw2, g2, b2, nullptr, pe2, nullptr, 0, 1);
    convh_k<64, false, 1><<<dim3(8, 32), 512, SM64B>>>(
        pe2, pw3, g3, b3, nullptr, nullptr, px, 0, 1);
    h0t0_k<<<dim3(512, 4), 256>>>(px, ph0 + HSZ);                 // h0 parity 1

    // ---- fork: stream A = h0 chain, stream B = up0/h1 chain ----
    cudaEventRecord(ev[0], 0);
    cudaStreamWaitEvent(sA, ev[0], 0);
    cudaStreamWaitEvent(sB, ev[0], 0);

    // stream B: up_0 conv (reads h0 parity1), then h1t0
    convh_k<64, false, 1><<<dim3(8, 4), 512, SM64B, sB>>>(
        ph0 + HSZ, pwul, gul, bul, nullptr, nullptr, pup, 0, 9);
    cudaEventRecord(ev[1], sB);                     // up0 done (WAR guard)
    h1t0_k<<<dim3(512, 4), 256, 0, sB>>>(pup, ph1 + HSZ, out);

    // recurrent steps t = 1..7
    // ev[2+t]  : h0(t) done      (A -> B, RAW for fused(t))
    // ev[10+t] : fused(t) done   (B -> A, WAR for h0(t+2))
    for (int t = 1; t < 8; t++) {
        int rp = t & 1, wpp = 1 - rp;
        // ---- stream A: h0(t) ----
        if (t == 2) cudaStreamWaitEvent(sA, ev[1], 0);        // up0 read of h0p1
        if (t >= 3) cudaStreamWaitEvent(sA, ev[10 + t - 2], 0); // fused(t-2) read
        convh_k<64, true, 2><<<dim3(8, 36), 512, SM64B, sA>>>(
            ph0 + rp * HSZ, pwh0, nullptr, nullptr, px,
            ph0 + wpp * HSZ, nullptr, t, 1);
        cudaEventRecord(ev[2 + t], sA);
        // ---- stream B: fused(t) ----
        cudaStreamWaitEvent(sB, ev[2 + t], 0);                // needs h0(t)
        convfuse_k<<<dim3(8, 36), 512, SM64B, sB>>>(
            ph0 + wpp * HSZ, ph1 + rp * HSZ, pwul, pwh1,
            gul, bul, ph1 + wpp * HSZ, out, t);
        cudaEventRecord(ev[10 + t], sB);
    }

    // ---- join back to the captured stream ----
    cudaEventRecord(ev[20], sA);
    cudaEventRecord(ev[21], sB);
    cudaStreamWaitEvent(0, ev[20], 0);
    cudaStreamWaitEvent(0, ev[21], 0);
}